// round 1
// baseline (speedup 1.0000x reference)
#include <cuda_runtime.h>
#include <math.h>
#include <stdint.h>

// ---------------- problem constants ----------------
constexpr int B_   = 4;
constexpr int S_   = 2048;
constexpr int D_   = 1024;
constexpr int H_   = 16;
constexpr int DK_  = 64;
constexpr int DFF_ = 4096;
constexpr int L_   = 6;
constexpr int BS_  = B_ * S_;   // 8192 rows

// ---------------- scratch (static device globals; no allocs allowed) ------
__device__ float g_h  [(size_t)BS_ * D_];
__device__ float g_q  [(size_t)BS_ * D_];
__device__ float g_k  [(size_t)BS_ * D_];
__device__ float g_v  [(size_t)BS_ * D_];
__device__ float g_ctx[(size_t)BS_ * D_];
__device__ float g_p  [(size_t)BS_ * D_];
__device__ float g_ff [(size_t)BS_ * DFF_];

// ---------------- embedding + positional encoding ----------------
__global__ void embed_kernel(const int* __restrict__ x,
                             const float* __restrict__ emb,
                             float* __restrict__ h) {
    int idx = blockIdx.x * blockDim.x + threadIdx.x;   // over BS_*D_
    int row = idx >> 10;          // / D_
    int d   = idx & (D_ - 1);
    int tok = x[row];
    int s   = row & (S_ - 1);     // position within sequence
    float val = emb[(size_t)tok * D_ + d] * 32.0f;     // sqrt(1024)
    int i2 = d & ~1;
    // div = exp(i2 * (-ln(10000)/1024))
    float div = expf((float)i2 * (-0.00899447301960227f));
    float ang = (float)s * div;
    float pe = (d & 1) ? cosf(ang) : sinf(ang);
    h[idx] = val + pe;
}

// ---------------- tiled fp32 GEMM: C = A @ W + bias (opt ReLU) ------------
// A: (M,K) row-major, W: (K,N) row-major, C: (M,N)
// BM=BN=128, BK=8, 256 threads, 8x8 per thread (split 4+4 for vectorization)
template<int RELU>
__global__ __launch_bounds__(256) void gemm_kernel(
    const float* __restrict__ A, const float* __restrict__ W,
    const float* __restrict__ bias, float* __restrict__ C,
    int M, int N, int K) {
    __shared__ float As[8][128];
    __shared__ float Bs[8][128];
    const int t  = threadIdx.x;
    const int m0 = blockIdx.y * 128;
    const int n0 = blockIdx.x * 128;
    const int ty = t >> 4, tx = t & 15;
    const int aRow = t >> 1,  aCol = (t & 1) << 2;
    const int bRow = t >> 5,  bCol = (t & 31) << 2;

    const float* Ap = A + (size_t)(m0 + aRow) * K + aCol;
    const float* Bp = W + (size_t)bRow * N + n0 + bCol;

    float acc[8][8];
    #pragma unroll
    for (int i = 0; i < 8; i++)
        #pragma unroll
        for (int j = 0; j < 8; j++) acc[i][j] = 0.0f;

    for (int k0 = 0; k0 < K; k0 += 8) {
        float4 av = *(const float4*)(Ap + k0);
        float4 bv = *(const float4*)(Bp + (size_t)k0 * N);
        As[aCol + 0][aRow] = av.x;
        As[aCol + 1][aRow] = av.y;
        As[aCol + 2][aRow] = av.z;
        As[aCol + 3][aRow] = av.w;
        *(float4*)&Bs[bRow][bCol] = bv;
        __syncthreads();
        #pragma unroll
        for (int kk = 0; kk < 8; kk++) {
            float a[8], b[8];
            *(float4*)&a[0] = *(const float4*)&As[kk][ty * 4];
            *(float4*)&a[4] = *(const float4*)&As[kk][64 + ty * 4];
            *(float4*)&b[0] = *(const float4*)&Bs[kk][tx * 4];
            *(float4*)&b[4] = *(const float4*)&Bs[kk][64 + tx * 4];
            #pragma unroll
            for (int i = 0; i < 8; i++)
                #pragma unroll
                for (int j = 0; j < 8; j++)
                    acc[i][j] += a[i] * b[j];
        }
        __syncthreads();
    }

    #pragma unroll
    for (int i = 0; i < 8; i++) {
        int row = m0 + ((i < 4) ? (ty * 4 + i) : (64 + ty * 4 + i - 4));
        #pragma unroll
        for (int jc = 0; jc < 2; jc++) {
            int col = n0 + jc * 64 + tx * 4;
            float4 bb = *(const float4*)&bias[col];
            float4 o;
            o.x = acc[i][jc * 4 + 0] + bb.x;
            o.y = acc[i][jc * 4 + 1] + bb.y;
            o.z = acc[i][jc * 4 + 2] + bb.z;
            o.w = acc[i][jc * 4 + 3] + bb.w;
            if (RELU) {
                o.x = fmaxf(o.x, 0.0f); o.y = fmaxf(o.y, 0.0f);
                o.z = fmaxf(o.z, 0.0f); o.w = fmaxf(o.w, 0.0f);
            }
            *(float4*)&C[(size_t)row * N + col] = o;
        }
    }
}

// ---------------- flash attention ----------------
// grid (S/128, H, B), 256 threads. Q tile 128, KV tile 128, DK=64.
// Thread (ty,tx): q rows {ty*4..+3, 64+ty*4..+3}, k cols {tx*4..+3, 64+tx*4..+3},
// output dims {tx*4..+3}.
constexpr int ATTN_SMEM_FLOATS = 128 * 65 * 2 + 128 * 64 + 128 * 132;
constexpr int ATTN_SMEM_BYTES  = ATTN_SMEM_FLOATS * 4 + S_ * 4;

__global__ __launch_bounds__(256) void attn_kernel(
    const float* __restrict__ Q, const float* __restrict__ K,
    const float* __restrict__ V, const int* __restrict__ mask,
    float* __restrict__ ctx) {
    extern __shared__ float sm[];
    float* Qs = sm;                     // [128][65]
    float* Ks = Qs + 128 * 65;          // [128][65]
    float* Vs = Ks + 128 * 65;          // [128][64]
    float* Ps = Vs + 128 * 64;          // [128][132]
    int*  msk = (int*)(Ps + 128 * 132); // [2048]

    const int qt = blockIdx.x, h = blockIdx.y, b = blockIdx.z;
    const int t = threadIdx.x;
    const int ty = t >> 4, tx = t & 15;

    int qrow[8];
    #pragma unroll
    for (int qi = 0; qi < 8; qi++)
        qrow[qi] = (qi < 4) ? (ty * 4 + qi) : (64 + ty * 4 + qi - 4);

    for (int i = t; i < S_; i += 256) msk[i] = mask[b * S_ + i];
    for (int i = t; i < 128 * 64; i += 256) {
        int r = i >> 6, d = i & 63;
        Qs[r * 65 + d] =
            Q[(size_t)(b * S_ + qt * 128 + r) * D_ + h * 64 + d] * 0.125f;
    }

    float m_i[8], l_i[8], o[8][4];
    #pragma unroll
    for (int qi = 0; qi < 8; qi++) {
        m_i[qi] = -INFINITY; l_i[qi] = 0.0f;
        #pragma unroll
        for (int j = 0; j < 4; j++) o[qi][j] = 0.0f;
    }
    __syncthreads();

    for (int kt = 0; kt < S_ / 128; kt++) {
        if (kt) __syncthreads();
        for (int i = t; i < 128 * 64; i += 256) {
            int r = i >> 6, d = i & 63;
            size_t g = (size_t)(b * S_ + kt * 128 + r) * D_ + h * 64 + d;
            Ks[r * 65 + d] = K[g];
            Vs[r * 64 + d] = V[g];
        }
        __syncthreads();

        // scores: acc[qi][kj]
        float acc[8][8];
        #pragma unroll
        for (int qi = 0; qi < 8; qi++)
            #pragma unroll
            for (int kj = 0; kj < 8; kj++) acc[qi][kj] = 0.0f;

        for (int d = 0; d < 64; d++) {
            float qa[8], kb[8];
            #pragma unroll
            for (int qi = 0; qi < 8; qi++) qa[qi] = Qs[qrow[qi] * 65 + d];
            #pragma unroll
            for (int kj = 0; kj < 8; kj++) {
                int kc = (kj < 4) ? (tx * 4 + kj) : (64 + tx * 4 + kj - 4);
                kb[kj] = Ks[kc * 65 + d];
            }
            #pragma unroll
            for (int qi = 0; qi < 8; qi++)
                #pragma unroll
                for (int kj = 0; kj < 8; kj++)
                    acc[qi][kj] += qa[qi] * kb[kj];
        }

        // mask (per key column)
        bool mz[8];
        #pragma unroll
        for (int kj = 0; kj < 8; kj++) {
            int kc = (kj < 4) ? (tx * 4 + kj) : (64 + tx * 4 + kj - 4);
            mz[kj] = (msk[kt * 128 + kc] == 0);
        }

        // online softmax update + write P tile
        #pragma unroll
        for (int qi = 0; qi < 8; qi++) {
            float rowmax = -INFINITY;
            #pragma unroll
            for (int kj = 0; kj < 8; kj++) {
                float s = mz[kj] ? -1e9f : acc[qi][kj];
                acc[qi][kj] = s;
                rowmax = fmaxf(rowmax, s);
            }
            #pragma unroll
            for (int off = 8; off; off >>= 1)
                rowmax = fmaxf(rowmax, __shfl_xor_sync(0xffffffffu, rowmax, off));
            float mn   = fmaxf(m_i[qi], rowmax);
            float corr = __expf(m_i[qi] - mn);
            m_i[qi] = mn;
            float rs = 0.0f;
            #pragma unroll
            for (int kj = 0; kj < 8; kj++) {
                float p = __expf(acc[qi][kj] - mn);
                acc[qi][kj] = p;
                rs += p;
            }
            #pragma unroll
            for (int off = 8; off; off >>= 1)
                rs += __shfl_xor_sync(0xffffffffu, rs, off);
            l_i[qi] = l_i[qi] * corr + rs;
            #pragma unroll
            for (int j = 0; j < 4; j++) o[qi][j] *= corr;

            float4 p0 = make_float4(acc[qi][0], acc[qi][1], acc[qi][2], acc[qi][3]);
            float4 p1 = make_float4(acc[qi][4], acc[qi][5], acc[qi][6], acc[qi][7]);
            *(float4*)&Ps[qrow[qi] * 132 + tx * 4]      = p0;
            *(float4*)&Ps[qrow[qi] * 132 + 64 + tx * 4] = p1;
        }
        __syncthreads();

        // PV accumulate: o[qi][j] += P[q][k] * V[k][tx*4+j]
        #pragma unroll 4
        for (int k = 0; k < 128; k++) {
            float4 v4 = *(const float4*)&Vs[k * 64 + tx * 4];
            #pragma unroll
            for (int qi = 0; qi < 8; qi++) {
                float p = Ps[qrow[qi] * 132 + k];
                o[qi][0] += p * v4.x;
                o[qi][1] += p * v4.y;
                o[qi][2] += p * v4.z;
                o[qi][3] += p * v4.w;
            }
        }
    }

    #pragma unroll
    for (int qi = 0; qi < 8; qi++) {
        float inv = 1.0f / l_i[qi];
        float4 r = make_float4(o[qi][0] * inv, o[qi][1] * inv,
                               o[qi][2] * inv, o[qi][3] * inv);
        *(float4*)&ctx[(size_t)(b * S_ + qt * 128 + qrow[qi]) * D_ +
                       h * 64 + tx * 4] = r;
    }
}

// ---------------- fused residual + LayerNorm ----------------
// out[row] = LN(a[row] + (r ? r[row] : 0)) * g + be ; one block per row.
__global__ __launch_bounds__(256) void ln_kernel(
    const float* __restrict__ a, const float* __restrict__ r,
    const float* __restrict__ g, const float* __restrict__ be,
    float* __restrict__ out) {
    int row = blockIdx.x;
    int t = threadIdx.x;
    float4 x = ((const float4*)a)[(size_t)row * 256 + t];
    if (r) {
        float4 y = ((const float4*)r)[(size_t)row * 256 + t];
        x.x += y.x; x.y += y.y; x.z += y.z; x.w += y.w;
    }
    float s  = x.x + x.y + x.z + x.w;
    float ss = x.x * x.x + x.y * x.y + x.z * x.z + x.w * x.w;
    #pragma unroll
    for (int off = 16; off; off >>= 1) {
        s  += __shfl_xor_sync(0xffffffffu, s,  off);
        ss += __shfl_xor_sync(0xffffffffu, ss, off);
    }
    __shared__ float wsum[8], wsq[8];
    int warp = t >> 5, lane = t & 31;
    if (lane == 0) { wsum[warp] = s; wsq[warp] = ss; }
    __syncthreads();
    s = 0.0f; ss = 0.0f;
    #pragma unroll
    for (int i = 0; i < 8; i++) { s += wsum[i]; ss += wsq[i]; }
    float mean = s * (1.0f / 1024.0f);
    float var  = ss * (1.0f / 1024.0f) - mean * mean;
    float rstd = rsqrtf(var + 1e-5f);
    float4 gg = ((const float4*)g)[t];
    float4 bb = ((const float4*)be)[t];
    float4 o;
    o.x = (x.x - mean) * rstd * gg.x + bb.x;
    o.y = (x.y - mean) * rstd * gg.y + bb.y;
    o.z = (x.z - mean) * rstd * gg.z + bb.z;
    o.w = (x.w - mean) * rstd * gg.w + bb.w;
    ((float4*)out)[(size_t)row * 256 + t] = o;
}

// ---------------- launch ----------------
extern "C" void kernel_launch(void* const* d_in, const int* in_sizes, int n_in,
                              void* d_out, int out_size) {
    (void)in_sizes; (void)n_in; (void)out_size;
    const int*   x    = (const int*)  d_in[0];
    const int*   mask = (const int*)  d_in[1];
    const float* emb  = (const float*)d_in[2];
    const float* wq   = (const float*)d_in[3];
    const float* bq   = (const float*)d_in[4];
    const float* wk   = (const float*)d_in[5];
    const float* bk   = (const float*)d_in[6];
    const float* wv   = (const float*)d_in[7];
    const float* bv   = (const float*)d_in[8];
    const float* wo   = (const float*)d_in[9];
    const float* bo   = (const float*)d_in[10];
    const float* w1   = (const float*)d_in[11];
    const float* b1   = (const float*)d_in[12];
    const float* w2   = (const float*)d_in[13];
    const float* b2   = (const float*)d_in[14];
    const float* g1   = (const float*)d_in[15];
    const float* be1  = (const float*)d_in[16];
    const float* g2   = (const float*)d_in[17];
    const float* be2  = (const float*)d_in[18];
    const float* gf   = (const float*)d_in[19];
    const float* bf   = (const float*)d_in[20];
    float* out = (float*)d_out;

    float *gh, *gq, *gk, *gv, *gctx, *gp, *gff;
    cudaGetSymbolAddress((void**)&gh,   g_h);
    cudaGetSymbolAddress((void**)&gq,   g_q);
    cudaGetSymbolAddress((void**)&gk,   g_k);
    cudaGetSymbolAddress((void**)&gv,   g_v);
    cudaGetSymbolAddress((void**)&gctx, g_ctx);
    cudaGetSymbolAddress((void**)&gp,   g_p);
    cudaGetSymbolAddress((void**)&gff,  g_ff);

    cudaFuncSetAttribute(attn_kernel,
                         cudaFuncAttributeMaxDynamicSharedMemorySize,
                         ATTN_SMEM_BYTES);

    embed_kernel<<<(BS_ * D_) / 256, 256>>>(x, emb, gh);

    for (int l = 0; l < L_; l++) {
        const size_t wOff = (size_t)l * D_ * D_;
        gemm_kernel<0><<<dim3(8, 64), 256>>>(gh,   wq + wOff, bq + l * D_, gq,   BS_, D_, D_);
        gemm_kernel<0><<<dim3(8, 64), 256>>>(gh,   wk + wOff, bk + l * D_, gk,   BS_, D_, D_);
        gemm_kernel<0><<<dim3(8, 64), 256>>>(gh,   wv + wOff, bv + l * D_, gv,   BS_, D_, D_);
        attn_kernel<<<dim3(S_ / 128, H_, B_), 256, ATTN_SMEM_BYTES>>>(gq, gk, gv, mask, gctx);
        gemm_kernel<0><<<dim3(8, 64), 256>>>(gctx, wo + wOff, bo + l * D_, gp,   BS_, D_, D_);
        ln_kernel<<<BS_, 256>>>(gh, gp, g1 + l * D_, be1 + l * D_, gh);
        gemm_kernel<1><<<dim3(32, 64), 256>>>(gh,  w1 + (size_t)l * D_ * DFF_, b1 + l * DFF_, gff, BS_, DFF_, D_);
        gemm_kernel<0><<<dim3(8, 64), 256>>>(gff,  w2 + (size_t)l * DFF_ * D_, b2 + l * D_,  gp,  BS_, D_, DFF_);
        ln_kernel<<<BS_, 256>>>(gh, gp, g2 + l * D_, be2 + l * D_, gh);
    }
    ln_kernel<<<BS_, 256>>>(gh, nullptr, gf, bf, out);
}

// round 2
// speedup vs baseline: 1.5756x; 1.5756x over previous
#include <cuda_runtime.h>
#include <math.h>
#include <stdint.h>

// ---------------- problem constants ----------------
constexpr int B_   = 4;
constexpr int S_   = 2048;
constexpr int D_   = 1024;
constexpr int H_   = 16;
constexpr int DFF_ = 4096;
constexpr int L_   = 6;
constexpr int BS_  = B_ * S_;   // 8192 rows

// ---------------- scratch (static device globals; no allocs allowed) ------
__device__ float g_h  [(size_t)BS_ * D_];
__device__ float g_q  [(size_t)BS_ * D_];
__device__ float g_k  [(size_t)BS_ * D_];
__device__ float g_v  [(size_t)BS_ * D_];
__device__ float g_ctx[(size_t)BS_ * D_];
__device__ float g_p  [(size_t)BS_ * D_];
__device__ float g_ff [(size_t)BS_ * DFF_];

// ---------------- embedding + positional encoding ----------------
__global__ void embed_kernel(const int* __restrict__ x,
                             const float* __restrict__ emb,
                             float* __restrict__ h) {
    int idx = blockIdx.x * blockDim.x + threadIdx.x;   // over BS_*D_
    int row = idx >> 10;          // / D_
    int d   = idx & (D_ - 1);
    int tok = x[row];
    int s   = row & (S_ - 1);     // position within sequence
    float val = emb[(size_t)tok * D_ + d] * 32.0f;     // sqrt(1024)
    int i2 = d & ~1;
    float div = expf((float)i2 * (-0.00899447301960227f));
    float ang = (float)s * div;
    float pe = (d & 1) ? cosf(ang) : sinf(ang);
    h[idx] = val + pe;
}

// ---------------- tf32 tensor-core GEMM ----------------
// C = A @ W + bias (opt ReLU). A:(M,K) rm, W:(K,N) rm, C:(M,N) rm.
// Block tile 128x128, K-tile 32, 256 threads = 8 warps in 2x4, warp tile 64x32.
// mma.sync.aligned.m16n8k8.row.col.f32.tf32.tf32.f32
// Smem: XOR-swizzled so transpose-STS and all fragment LDS are conflict-free.
//   A phys: k*128 + ( m ^ ((k&3)<<3) ^ (((k>>2)&7)<<2) )
//   B phys: k*128 + ( n ^ ((k&3)<<3) )

__device__ __forceinline__ uint32_t f2tf32(float x) {
    uint32_t r;
    asm("cvt.rna.tf32.f32 %0, %1;" : "=r"(r) : "f"(x));
    return r;
}

__device__ __forceinline__ void mma_tf32(float* c, const uint32_t* a,
                                         const uint32_t* b) {
    asm volatile(
        "mma.sync.aligned.m16n8k8.row.col.f32.tf32.tf32.f32 "
        "{%0,%1,%2,%3}, {%4,%5,%6,%7}, {%8,%9}, {%0,%1,%2,%3};\n"
        : "+f"(c[0]), "+f"(c[1]), "+f"(c[2]), "+f"(c[3])
        : "r"(a[0]), "r"(a[1]), "r"(a[2]), "r"(a[3]), "r"(b[0]), "r"(b[1]));
}

constexpr int GEMM_SMEM_BYTES = 4 * 32 * 128 * 4;  // 2 bufs x (A+B) x 16KB

template<int RELU>
__global__ __launch_bounds__(256) void gemm_tf32(
    const float* __restrict__ A, const float* __restrict__ W,
    const float* __restrict__ bias, float* __restrict__ C,
    int M, int N, int K) {
    extern __shared__ uint32_t sm_u[];
    uint32_t* AsAll = sm_u;              // [2][32*128]
    uint32_t* BsAll = sm_u + 2 * 4096;   // [2][32*128]

    const int t    = threadIdx.x;
    const int m0   = blockIdx.y * 128;
    const int n0   = blockIdx.x * 128;
    const int warp = t >> 5, lane = t & 31;
    const int wm   = warp >> 2, wn = warp & 3;   // 2 x 4
    const int g    = lane >> 2, tg = lane & 3;

    // global->reg staging mapping
    const int aRow = t >> 3;           // 0..31 (then +32 per iter)
    const int aKc  = t & 7;            // float4 index along K
    const int bK   = t >> 5;           // 0..7 (then +8 per iter)
    const int bNc  = t & 31;           // float4 index along N

    const float* Aptr = A + (size_t)m0 * K;
    const float* Wptr = W + n0;

    float acc[4][4][4];
    #pragma unroll
    for (int i = 0; i < 4; i++)
        #pragma unroll
        for (int j = 0; j < 4; j++)
            #pragma unroll
            for (int r = 0; r < 4; r++) acc[i][j][r] = 0.0f;

    float4 stA[4], stB[4];

    auto ldg_tile = [&](int k0) {
        #pragma unroll
        for (int i = 0; i < 4; i++) {
            int row = aRow + i * 32;
            stA[i] = *(const float4*)(Aptr + (size_t)row * K + k0 + aKc * 4);
        }
        #pragma unroll
        for (int i = 0; i < 4; i++) {
            int k = bK + i * 8;
            stB[i] = *(const float4*)(Wptr + (size_t)(k0 + k) * N + bNc * 4);
        }
    };

    auto sts_tile = [&](int buf) {
        uint32_t* Ad = AsAll + buf * 4096;
        uint32_t* Bd = BsAll + buf * 4096;
        #pragma unroll
        for (int i = 0; i < 4; i++) {
            int row = aRow + i * 32;
            float v[4] = {stA[i].x, stA[i].y, stA[i].z, stA[i].w};
            #pragma unroll
            for (int j = 0; j < 4; j++) {
                int k   = aKc * 4 + j;
                int fsw = ((k & 3) << 3) ^ (((k >> 2) & 7) << 2);
                Ad[k * 128 + (row ^ fsw)] = f2tf32(v[j]);
            }
        }
        #pragma unroll
        for (int i = 0; i < 4; i++) {
            int k    = bK + i * 8;
            int phys = k * 128 + ((bNc * 4) ^ ((k & 3) << 3));
            Bd[phys + 0] = f2tf32(stB[i].x);
            Bd[phys + 1] = f2tf32(stB[i].y);
            Bd[phys + 2] = f2tf32(stB[i].z);
            Bd[phys + 3] = f2tf32(stB[i].w);
        }
    };

    auto compute = [&](int buf) {
        const uint32_t* Ab = AsAll + buf * 4096;
        const uint32_t* Bb = BsAll + buf * 4096;
        #pragma unroll
        for (int ks = 0; ks < 4; ks++) {
            const int kb  = ks * 8;
            const int kA0 = kb + tg;
            const int kA1 = kb + tg + 4;
            const int f0  = (tg << 3) ^ (((kA0 >> 2) & 7) << 2);
            const int f1  = (tg << 3) ^ (((kA1 >> 2) & 7) << 2);
            uint32_t afr[4][4];
            #pragma unroll
            for (int mf = 0; mf < 4; mf++) {
                int mb = wm * 64 + mf * 16;
                afr[mf][0] = Ab[kA0 * 128 + ((mb + g)     ^ f0)];
                afr[mf][1] = Ab[kA0 * 128 + ((mb + 8 + g) ^ f0)];
                afr[mf][2] = Ab[kA1 * 128 + ((mb + g)     ^ f1)];
                afr[mf][3] = Ab[kA1 * 128 + ((mb + 8 + g) ^ f1)];
            }
            uint32_t bfr[4][2];
            #pragma unroll
            for (int nf = 0; nf < 4; nf++) {
                int nb = wn * 32 + nf * 8 + g;
                bfr[nf][0] = Bb[kA0 * 128 + (nb ^ (tg << 3))];
                bfr[nf][1] = Bb[kA1 * 128 + (nb ^ (tg << 3))];
            }
            #pragma unroll
            for (int mf = 0; mf < 4; mf++)
                #pragma unroll
                for (int nf = 0; nf < 4; nf++)
                    mma_tf32(acc[mf][nf], afr[mf], bfr[nf]);
        }
    };

    const int nk = K >> 5;
    ldg_tile(0);
    sts_tile(0);
    __syncthreads();

    for (int kt = 0; kt < nk; kt++) {
        if (kt + 1 < nk) ldg_tile((kt + 1) << 5);
        compute(kt & 1);
        if (kt + 1 < nk) sts_tile((kt + 1) & 1);
        __syncthreads();
    }

    // epilogue
    #pragma unroll
    for (int mf = 0; mf < 4; mf++) {
        int r0 = m0 + wm * 64 + mf * 16 + g;
        int r1 = r0 + 8;
        #pragma unroll
        for (int nf = 0; nf < 4; nf++) {
            int col = n0 + wn * 32 + nf * 8 + tg * 2;
            float2 bb = *(const float2*)&bias[col];
            float2 o0, o1;
            o0.x = acc[mf][nf][0] + bb.x;
            o0.y = acc[mf][nf][1] + bb.y;
            o1.x = acc[mf][nf][2] + bb.x;
            o1.y = acc[mf][nf][3] + bb.y;
            if (RELU) {
                o0.x = fmaxf(o0.x, 0.0f); o0.y = fmaxf(o0.y, 0.0f);
                o1.x = fmaxf(o1.x, 0.0f); o1.y = fmaxf(o1.y, 0.0f);
            }
            *(float2*)&C[(size_t)r0 * N + col] = o0;
            *(float2*)&C[(size_t)r1 * N + col] = o1;
        }
    }
}

// ---------------- flash attention (unchanged from R1) ----------------
constexpr int ATTN_SMEM_FLOATS = 128 * 65 * 2 + 128 * 64 + 128 * 132;
constexpr int ATTN_SMEM_BYTES  = ATTN_SMEM_FLOATS * 4 + S_ * 4;

__global__ __launch_bounds__(256) void attn_kernel(
    const float* __restrict__ Q, const float* __restrict__ K,
    const float* __restrict__ V, const int* __restrict__ mask,
    float* __restrict__ ctx) {
    extern __shared__ float sm[];
    float* Qs = sm;                     // [128][65]
    float* Ks = Qs + 128 * 65;          // [128][65]
    float* Vs = Ks + 128 * 65;          // [128][64]
    float* Ps = Vs + 128 * 64;          // [128][132]
    int*  msk = (int*)(Ps + 128 * 132); // [2048]

    const int qt = blockIdx.x, h = blockIdx.y, b = blockIdx.z;
    const int t = threadIdx.x;
    const int ty = t >> 4, tx = t & 15;

    int qrow[8];
    #pragma unroll
    for (int qi = 0; qi < 8; qi++)
        qrow[qi] = (qi < 4) ? (ty * 4 + qi) : (64 + ty * 4 + qi - 4);

    for (int i = t; i < S_; i += 256) msk[i] = mask[b * S_ + i];
    for (int i = t; i < 128 * 64; i += 256) {
        int r = i >> 6, d = i & 63;
        Qs[r * 65 + d] =
            Q[(size_t)(b * S_ + qt * 128 + r) * D_ + h * 64 + d] * 0.125f;
    }

    float m_i[8], l_i[8], o[8][4];
    #pragma unroll
    for (int qi = 0; qi < 8; qi++) {
        m_i[qi] = -INFINITY; l_i[qi] = 0.0f;
        #pragma unroll
        for (int j = 0; j < 4; j++) o[qi][j] = 0.0f;
    }
    __syncthreads();

    for (int kt = 0; kt < S_ / 128; kt++) {
        if (kt) __syncthreads();
        for (int i = t; i < 128 * 64; i += 256) {
            int r = i >> 6, d = i & 63;
            size_t gofs = (size_t)(b * S_ + kt * 128 + r) * D_ + h * 64 + d;
            Ks[r * 65 + d] = K[gofs];
            Vs[r * 64 + d] = V[gofs];
        }
        __syncthreads();

        float acc[8][8];
        #pragma unroll
        for (int qi = 0; qi < 8; qi++)
            #pragma unroll
            for (int kj = 0; kj < 8; kj++) acc[qi][kj] = 0.0f;

        for (int d = 0; d < 64; d++) {
            float qa[8], kb[8];
            #pragma unroll
            for (int qi = 0; qi < 8; qi++) qa[qi] = Qs[qrow[qi] * 65 + d];
            #pragma unroll
            for (int kj = 0; kj < 8; kj++) {
                int kc = (kj < 4) ? (tx * 4 + kj) : (64 + tx * 4 + kj - 4);
                kb[kj] = Ks[kc * 65 + d];
            }
            #pragma unroll
            for (int qi = 0; qi < 8; qi++)
                #pragma unroll
                for (int kj = 0; kj < 8; kj++)
                    acc[qi][kj] += qa[qi] * kb[kj];
        }

        bool mz[8];
        #pragma unroll
        for (int kj = 0; kj < 8; kj++) {
            int kc = (kj < 4) ? (tx * 4 + kj) : (64 + tx * 4 + kj - 4);
            mz[kj] = (msk[kt * 128 + kc] == 0);
        }

        #pragma unroll
        for (int qi = 0; qi < 8; qi++) {
            float rowmax = -INFINITY;
            #pragma unroll
            for (int kj = 0; kj < 8; kj++) {
                float s = mz[kj] ? -1e9f : acc[qi][kj];
                acc[qi][kj] = s;
                rowmax = fmaxf(rowmax, s);
            }
            #pragma unroll
            for (int off = 8; off; off >>= 1)
                rowmax = fmaxf(rowmax, __shfl_xor_sync(0xffffffffu, rowmax, off));
            float mn   = fmaxf(m_i[qi], rowmax);
            float corr = __expf(m_i[qi] - mn);
            m_i[qi] = mn;
            float rs = 0.0f;
            #pragma unroll
            for (int kj = 0; kj < 8; kj++) {
                float p = __expf(acc[qi][kj] - mn);
                acc[qi][kj] = p;
                rs += p;
            }
            #pragma unroll
            for (int off = 8; off; off >>= 1)
                rs += __shfl_xor_sync(0xffffffffu, rs, off);
            l_i[qi] = l_i[qi] * corr + rs;
            #pragma unroll
            for (int j = 0; j < 4; j++) o[qi][j] *= corr;

            float4 p0 = make_float4(acc[qi][0], acc[qi][1], acc[qi][2], acc[qi][3]);
            float4 p1 = make_float4(acc[qi][4], acc[qi][5], acc[qi][6], acc[qi][7]);
            *(float4*)&Ps[qrow[qi] * 132 + tx * 4]      = p0;
            *(float4*)&Ps[qrow[qi] * 132 + 64 + tx * 4] = p1;
        }
        __syncthreads();

        #pragma unroll 4
        for (int k = 0; k < 128; k++) {
            float4 v4 = *(const float4*)&Vs[k * 64 + tx * 4];
            #pragma unroll
            for (int qi = 0; qi < 8; qi++) {
                float p = Ps[qrow[qi] * 132 + k];
                o[qi][0] += p * v4.x;
                o[qi][1] += p * v4.y;
                o[qi][2] += p * v4.z;
                o[qi][3] += p * v4.w;
            }
        }
    }

    #pragma unroll
    for (int qi = 0; qi < 8; qi++) {
        float inv = 1.0f / l_i[qi];
        float4 r = make_float4(o[qi][0] * inv, o[qi][1] * inv,
                               o[qi][2] * inv, o[qi][3] * inv);
        *(float4*)&ctx[(size_t)(b * S_ + qt * 128 + qrow[qi]) * D_ +
                       h * 64 + tx * 4] = r;
    }
}

// ---------------- fused residual + LayerNorm ----------------
__global__ __launch_bounds__(256) void ln_kernel(
    const float* __restrict__ a, const float* __restrict__ r,
    const float* __restrict__ g, const float* __restrict__ be,
    float* __restrict__ out) {
    int row = blockIdx.x;
    int t = threadIdx.x;
    float4 x = ((const float4*)a)[(size_t)row * 256 + t];
    if (r) {
        float4 y = ((const float4*)r)[(size_t)row * 256 + t];
        x.x += y.x; x.y += y.y; x.z += y.z; x.w += y.w;
    }
    float s  = x.x + x.y + x.z + x.w;
    float ss = x.x * x.x + x.y * x.y + x.z * x.z + x.w * x.w;
    #pragma unroll
    for (int off = 16; off; off >>= 1) {
        s  += __shfl_xor_sync(0xffffffffu, s,  off);
        ss += __shfl_xor_sync(0xffffffffu, ss, off);
    }
    __shared__ float wsum[8], wsq[8];
    int warp = t >> 5, lane = t & 31;
    if (lane == 0) { wsum[warp] = s; wsq[warp] = ss; }
    __syncthreads();
    s = 0.0f; ss = 0.0f;
    #pragma unroll
    for (int i = 0; i < 8; i++) { s += wsum[i]; ss += wsq[i]; }
    float mean = s * (1.0f / 1024.0f);
    float var  = ss * (1.0f / 1024.0f) - mean * mean;
    float rstd = rsqrtf(var + 1e-5f);
    float4 gg = ((const float4*)g)[t];
    float4 bb = ((const float4*)be)[t];
    float4 o;
    o.x = (x.x - mean) * rstd * gg.x + bb.x;
    o.y = (x.y - mean) * rstd * gg.y + bb.y;
    o.z = (x.z - mean) * rstd * gg.z + bb.z;
    o.w = (x.w - mean) * rstd * gg.w + bb.w;
    ((float4*)out)[(size_t)row * 256 + t] = o;
}

// ---------------- launch ----------------
extern "C" void kernel_launch(void* const* d_in, const int* in_sizes, int n_in,
                              void* d_out, int out_size) {
    (void)in_sizes; (void)n_in; (void)out_size;
    const int*   x    = (const int*)  d_in[0];
    const int*   mask = (const int*)  d_in[1];
    const float* emb  = (const float*)d_in[2];
    const float* wq   = (const float*)d_in[3];
    const float* bq   = (const float*)d_in[4];
    const float* wk   = (const float*)d_in[5];
    const float* bk   = (const float*)d_in[6];
    const float* wv   = (const float*)d_in[7];
    const float* bv   = (const float*)d_in[8];
    const float* wo   = (const float*)d_in[9];
    const float* bo   = (const float*)d_in[10];
    const float* w1   = (const float*)d_in[11];
    const float* b1   = (const float*)d_in[12];
    const float* w2   = (const float*)d_in[13];
    const float* b2   = (const float*)d_in[14];
    const float* g1   = (const float*)d_in[15];
    const float* be1  = (const float*)d_in[16];
    const float* g2   = (const float*)d_in[17];
    const float* be2  = (const float*)d_in[18];
    const float* gf   = (const float*)d_in[19];
    const float* bf   = (const float*)d_in[20];
    float* out = (float*)d_out;

    float *gh, *gq, *gk, *gv, *gctx, *gp, *gff;
    cudaGetSymbolAddress((void**)&gh,   g_h);
    cudaGetSymbolAddress((void**)&gq,   g_q);
    cudaGetSymbolAddress((void**)&gk,   g_k);
    cudaGetSymbolAddress((void**)&gv,   g_v);
    cudaGetSymbolAddress((void**)&gctx, g_ctx);
    cudaGetSymbolAddress((void**)&gp,   g_p);
    cudaGetSymbolAddress((void**)&gff,  g_ff);

    cudaFuncSetAttribute(attn_kernel,
                         cudaFuncAttributeMaxDynamicSharedMemorySize,
                         ATTN_SMEM_BYTES);
    cudaFuncSetAttribute(gemm_tf32<0>,
                         cudaFuncAttributeMaxDynamicSharedMemorySize,
                         GEMM_SMEM_BYTES);
    cudaFuncSetAttribute(gemm_tf32<1>,
                         cudaFuncAttributeMaxDynamicSharedMemorySize,
                         GEMM_SMEM_BYTES);

    embed_kernel<<<(BS_ * D_) / 256, 256>>>(x, emb, gh);

    for (int l = 0; l < L_; l++) {
        const size_t wOff = (size_t)l * D_ * D_;
        gemm_tf32<0><<<dim3(8, 64), 256, GEMM_SMEM_BYTES>>>(gh,   wq + wOff, bq + l * D_, gq,   BS_, D_, D_);
        gemm_tf32<0><<<dim3(8, 64), 256, GEMM_SMEM_BYTES>>>(gh,   wk + wOff, bk + l * D_, gk,   BS_, D_, D_);
        gemm_tf32<0><<<dim3(8, 64), 256, GEMM_SMEM_BYTES>>>(gh,   wv + wOff, bv + l * D_, gv,   BS_, D_, D_);
        attn_kernel<<<dim3(S_ / 128, H_, B_), 256, ATTN_SMEM_BYTES>>>(gq, gk, gv, mask, gctx);
        gemm_tf32<0><<<dim3(8, 64), 256, GEMM_SMEM_BYTES>>>(gctx, wo + wOff, bo + l * D_, gp,   BS_, D_, D_);
        ln_kernel<<<BS_, 256>>>(gh, gp, g1 + l * D_, be1 + l * D_, gh);
        gemm_tf32<1><<<dim3(32, 64), 256, GEMM_SMEM_BYTES>>>(gh,  w1 + (size_t)l * D_ * DFF_, b1 + l * DFF_, gff, BS_, DFF_, D_);
        gemm_tf32<0><<<dim3(8, 64), 256, GEMM_SMEM_BYTES>>>(gff, w2 + (size_t)l * DFF_ * D_, b2 + l * D_,  gp,  BS_, D_, DFF_);
        ln_kernel<<<BS_, 256>>>(gh, gp, g2 + l * D_, be2 + l * D_, gh);
    }
    ln_kernel<<<BS_, 256>>>(gh, nullptr, gf, bf, out);
}

// round 3
// speedup vs baseline: 2.4773x; 1.5723x over previous
#include <cuda_runtime.h>
#include <math.h>
#include <stdint.h>

// ---------------- problem constants ----------------
constexpr int B_   = 4;
constexpr int S_   = 2048;
constexpr int D_   = 1024;
constexpr int H_   = 16;
constexpr int DFF_ = 4096;
constexpr int L_   = 6;
constexpr int BS_  = B_ * S_;   // 8192 rows

// ---------------- scratch ----------------
__device__ float g_h  [(size_t)BS_ * D_];
__device__ float g_q  [(size_t)BS_ * D_];
__device__ float g_k  [(size_t)BS_ * D_];
__device__ float g_v  [(size_t)BS_ * D_];
__device__ float g_ctx[(size_t)BS_ * D_];
__device__ float g_p  [(size_t)BS_ * D_];
__device__ float g_ff [(size_t)BS_ * DFF_];

// ---------------- embedding + positional encoding ----------------
__global__ void embed_kernel(const int* __restrict__ x,
                             const float* __restrict__ emb,
                             float* __restrict__ h) {
    int idx = blockIdx.x * blockDim.x + threadIdx.x;
    int row = idx >> 10;
    int d   = idx & (D_ - 1);
    int tok = x[row];
    int s   = row & (S_ - 1);
    float val = emb[(size_t)tok * D_ + d] * 32.0f;
    int i2 = d & ~1;
    float div = expf((float)i2 * (-0.00899447301960227f));
    float ang = (float)s * div;
    float pe = (d & 1) ? cosf(ang) : sinf(ang);
    h[idx] = val + pe;
}

// ---------------- tf32 helpers ----------------
__device__ __forceinline__ uint32_t f2tf32(float x) {
    uint32_t r;
    asm("cvt.rna.tf32.f32 %0, %1;" : "=r"(r) : "f"(x));
    return r;
}

__device__ __forceinline__ void mma_tf32(float* c, const uint32_t* a,
                                         const uint32_t* b) {
    asm volatile(
        "mma.sync.aligned.m16n8k8.row.col.f32.tf32.tf32.f32 "
        "{%0,%1,%2,%3}, {%4,%5,%6,%7}, {%8,%9}, {%0,%1,%2,%3};\n"
        : "+f"(c[0]), "+f"(c[1]), "+f"(c[2]), "+f"(c[3])
        : "r"(a[0]), "r"(a[1]), "r"(a[2]), "r"(a[3]), "r"(b[0]), "r"(b[1]));
}

// ---------------- tf32 GEMM (same as R2, body extracted) ----------------
constexpr int GEMM_SMEM_BYTES = 4 * 32 * 128 * 4;

template<int RELU>
__device__ __forceinline__ void gemm_body(
    const float* __restrict__ A, const float* __restrict__ W,
    const float* __restrict__ bias, float* __restrict__ C,
    int M, int N, int K) {
    extern __shared__ uint32_t sm_u[];
    uint32_t* AsAll = sm_u;
    uint32_t* BsAll = sm_u + 2 * 4096;

    const int t    = threadIdx.x;
    const int m0   = blockIdx.y * 128;
    const int n0   = blockIdx.x * 128;
    const int warp = t >> 5, lane = t & 31;
    const int wm   = warp >> 2, wn = warp & 3;
    const int g    = lane >> 2, tg = lane & 3;

    const int aRow = t >> 3;
    const int aKc  = t & 7;
    const int bK   = t >> 5;
    const int bNc  = t & 31;

    const float* Aptr = A + (size_t)m0 * K;
    const float* Wptr = W + n0;

    float acc[4][4][4];
    #pragma unroll
    for (int i = 0; i < 4; i++)
        #pragma unroll
        for (int j = 0; j < 4; j++)
            #pragma unroll
            for (int r = 0; r < 4; r++) acc[i][j][r] = 0.0f;

    float4 stA[4], stB[4];

    auto ldg_tile = [&](int k0) {
        #pragma unroll
        for (int i = 0; i < 4; i++) {
            int row = aRow + i * 32;
            stA[i] = *(const float4*)(Aptr + (size_t)row * K + k0 + aKc * 4);
        }
        #pragma unroll
        for (int i = 0; i < 4; i++) {
            int k = bK + i * 8;
            stB[i] = *(const float4*)(Wptr + (size_t)(k0 + k) * N + bNc * 4);
        }
    };

    auto sts_tile = [&](int buf) {
        uint32_t* Ad = AsAll + buf * 4096;
        uint32_t* Bd = BsAll + buf * 4096;
        #pragma unroll
        for (int i = 0; i < 4; i++) {
            int row = aRow + i * 32;
            float v[4] = {stA[i].x, stA[i].y, stA[i].z, stA[i].w};
            #pragma unroll
            for (int j = 0; j < 4; j++) {
                int k   = aKc * 4 + j;
                int fsw = ((k & 3) << 3) ^ (((k >> 2) & 7) << 2);
                Ad[k * 128 + (row ^ fsw)] = f2tf32(v[j]);
            }
        }
        #pragma unroll
        for (int i = 0; i < 4; i++) {
            int k    = bK + i * 8;
            int phys = k * 128 + ((bNc * 4) ^ ((k & 3) << 3));
            Bd[phys + 0] = f2tf32(stB[i].x);
            Bd[phys + 1] = f2tf32(stB[i].y);
            Bd[phys + 2] = f2tf32(stB[i].z);
            Bd[phys + 3] = f2tf32(stB[i].w);
        }
    };

    auto compute = [&](int buf) {
        const uint32_t* Ab = AsAll + buf * 4096;
        const uint32_t* Bb = BsAll + buf * 4096;
        #pragma unroll
        for (int ks = 0; ks < 4; ks++) {
            const int kb  = ks * 8;
            const int kA0 = kb + tg;
            const int kA1 = kb + tg + 4;
            const int f0  = (tg << 3) ^ (((kA0 >> 2) & 7) << 2);
            const int f1  = (tg << 3) ^ (((kA1 >> 2) & 7) << 2);
            uint32_t afr[4][4];
            #pragma unroll
            for (int mf = 0; mf < 4; mf++) {
                int mb = wm * 64 + mf * 16;
                afr[mf][0] = Ab[kA0 * 128 + ((mb + g)     ^ f0)];
                afr[mf][1] = Ab[kA0 * 128 + ((mb + 8 + g) ^ f0)];
                afr[mf][2] = Ab[kA1 * 128 + ((mb + g)     ^ f1)];
                afr[mf][3] = Ab[kA1 * 128 + ((mb + 8 + g) ^ f1)];
            }
            uint32_t bfr[4][2];
            #pragma unroll
            for (int nf = 0; nf < 4; nf++) {
                int nb = wn * 32 + nf * 8 + g;
                bfr[nf][0] = Bb[kA0 * 128 + (nb ^ (tg << 3))];
                bfr[nf][1] = Bb[kA1 * 128 + (nb ^ (tg << 3))];
            }
            #pragma unroll
            for (int mf = 0; mf < 4; mf++)
                #pragma unroll
                for (int nf = 0; nf < 4; nf++)
                    mma_tf32(acc[mf][nf], afr[mf], bfr[nf]);
        }
    };

    const int nk = K >> 5;
    ldg_tile(0);
    sts_tile(0);
    __syncthreads();

    for (int kt = 0; kt < nk; kt++) {
        if (kt + 1 < nk) ldg_tile((kt + 1) << 5);
        compute(kt & 1);
        if (kt + 1 < nk) sts_tile((kt + 1) & 1);
        __syncthreads();
    }

    #pragma unroll
    for (int mf = 0; mf < 4; mf++) {
        int r0 = m0 + wm * 64 + mf * 16 + g;
        int r1 = r0 + 8;
        #pragma unroll
        for (int nf = 0; nf < 4; nf++) {
            int col = n0 + wn * 32 + nf * 8 + tg * 2;
            float2 bb = *(const float2*)&bias[col];
            float2 o0, o1;
            o0.x = acc[mf][nf][0] + bb.x;
            o0.y = acc[mf][nf][1] + bb.y;
            o1.x = acc[mf][nf][2] + bb.x;
            o1.y = acc[mf][nf][3] + bb.y;
            if (RELU) {
                o0.x = fmaxf(o0.x, 0.0f); o0.y = fmaxf(o0.y, 0.0f);
                o1.x = fmaxf(o1.x, 0.0f); o1.y = fmaxf(o1.y, 0.0f);
            }
            *(float2*)&C[(size_t)r0 * N + col] = o0;
            *(float2*)&C[(size_t)r1 * N + col] = o1;
        }
    }
}

template<int RELU>
__global__ __launch_bounds__(256) void gemm_tf32(
    const float* __restrict__ A, const float* __restrict__ W,
    const float* __restrict__ bias, float* __restrict__ C,
    int M, int N, int K) {
    gemm_body<RELU>(A, W, bias, C, M, N, K);
}

// fused QKV: grid.z selects {q,k,v} projection
__global__ __launch_bounds__(256) void gemm_qkv(
    const float* __restrict__ A,
    const float* __restrict__ wq, const float* __restrict__ bq,
    const float* __restrict__ wk, const float* __restrict__ bk,
    const float* __restrict__ wv, const float* __restrict__ bv,
    float* __restrict__ oq, float* __restrict__ ok, float* __restrict__ ov) {
    const float* W; const float* bias; float* C;
    if (blockIdx.z == 0)      { W = wq; bias = bq; C = oq; }
    else if (blockIdx.z == 1) { W = wk; bias = bk; C = ok; }
    else                      { W = wv; bias = bv; C = ov; }
    gemm_body<0>(A, W, bias, C, BS_, D_, D_);
}

// ---------------- tensor-core flash attention ----------------
// grid (S/128, H, B), 256 threads = 8 warps; warp w owns q rows [16w,16w+16).
// QK^T and P*V via mma.m16n8k8 tf32. P round-trips smem (warp-private rows,
// only __syncwarp between softmax and PV).
constexpr int QLD = 68;    // Q/K smem row stride (conflict-free frag loads)
constexpr int VLD = 72;    // V smem row stride (8*tg+g distinct)
constexpr int PLD = 132;   // P smem row stride
constexpr int ATTN_SMEM_BYTES =
    (128 * QLD * 2 + 128 * VLD + 128 * PLD) * 4 + S_ * 4;

__global__ __launch_bounds__(256) void attn_mma(
    const float* __restrict__ Q, const float* __restrict__ K,
    const float* __restrict__ V, const int* __restrict__ mask,
    float* __restrict__ ctx) {
    extern __shared__ uint32_t sm[];
    uint32_t* Qs = sm;                    // [128][QLD]
    uint32_t* Ks = Qs + 128 * QLD;        // [128][QLD]
    uint32_t* Vs = Ks + 128 * QLD;        // [128][VLD]
    uint32_t* Ps = Vs + 128 * VLD;        // [128][PLD]
    int*     msk = (int*)(Ps + 128 * PLD);

    const int qt = blockIdx.x, h = blockIdx.y, b = blockIdx.z;
    const int t = threadIdx.x, w = t >> 5, lane = t & 31;
    const int g = lane >> 2, tg = lane & 3;
    const int r0 = w * 16 + g, r1 = r0 + 8;   // this thread's q rows (in tile)

    for (int i = t; i < S_; i += 256) msk[i] = mask[b * S_ + i];
    for (int i = t; i < 128 * 16; i += 256) {
        int r = i >> 4, c4 = (i & 15) << 2;
        float4 qv = *(const float4*)&Q[(size_t)(b * S_ + qt * 128 + r) * D_ +
                                       h * 64 + c4];
        uint32_t* dst = &Qs[r * QLD + c4];
        dst[0] = f2tf32(qv.x * 0.125f);
        dst[1] = f2tf32(qv.y * 0.125f);
        dst[2] = f2tf32(qv.z * 0.125f);
        dst[3] = f2tf32(qv.w * 0.125f);
    }

    float m_i[2] = {-INFINITY, -INFINITY};
    float l_i[2] = {0.0f, 0.0f};
    float o[8][4];
    #pragma unroll
    for (int nf = 0; nf < 8; nf++)
        #pragma unroll
        for (int r = 0; r < 4; r++) o[nf][r] = 0.0f;

    for (int kt = 0; kt < S_ / 128; kt++) {
        __syncthreads();   // Ks/Vs free (prev PV done), Q/msk ready on kt=0
        for (int i = t; i < 128 * 16; i += 256) {
            int r = i >> 4, c4 = (i & 15) << 2;
            size_t gofs = (size_t)(b * S_ + kt * 128 + r) * D_ + h * 64 + c4;
            float4 kv = *(const float4*)&K[gofs];
            float4 vv = *(const float4*)&V[gofs];
            uint32_t* kd = &Ks[r * QLD + c4];
            kd[0] = f2tf32(kv.x); kd[1] = f2tf32(kv.y);
            kd[2] = f2tf32(kv.z); kd[3] = f2tf32(kv.w);
            uint32_t* vd = &Vs[r * VLD + c4];
            vd[0] = f2tf32(vv.x); vd[1] = f2tf32(vv.y);
            vd[2] = f2tf32(vv.z); vd[3] = f2tf32(vv.w);
        }
        __syncthreads();

        // ---- S = Q K^T  (16 n-frags cover 128 kv cols) ----
        float s[16][4];
        #pragma unroll
        for (int nf = 0; nf < 16; nf++)
            #pragma unroll
            for (int r = 0; r < 4; r++) s[nf][r] = 0.0f;

        #pragma unroll
        for (int kb = 0; kb < 64; kb += 8) {
            uint32_t a[4];
            a[0] = Qs[r0 * QLD + kb + tg];
            a[1] = Qs[r1 * QLD + kb + tg];
            a[2] = Qs[r0 * QLD + kb + tg + 4];
            a[3] = Qs[r1 * QLD + kb + tg + 4];
            #pragma unroll
            for (int nf = 0; nf < 16; nf++) {
                uint32_t bf[2];
                bf[0] = Ks[(nf * 8 + g) * QLD + kb + tg];
                bf[1] = Ks[(nf * 8 + g) * QLD + kb + tg + 4];
                mma_tf32(s[nf], a, bf);
            }
        }

        // ---- masking + row max ----
        float mx0 = -INFINITY, mx1 = -INFINITY;
        #pragma unroll
        for (int nf = 0; nf < 16; nf++) {
            int c = kt * 128 + nf * 8 + 2 * tg;
            if (msk[c] == 0)     { s[nf][0] = -1e9f; s[nf][2] = -1e9f; }
            if (msk[c + 1] == 0) { s[nf][1] = -1e9f; s[nf][3] = -1e9f; }
            mx0 = fmaxf(mx0, fmaxf(s[nf][0], s[nf][1]));
            mx1 = fmaxf(mx1, fmaxf(s[nf][2], s[nf][3]));
        }
        #pragma unroll
        for (int off = 1; off <= 2; off <<= 1) {
            mx0 = fmaxf(mx0, __shfl_xor_sync(0xffffffffu, mx0, off));
            mx1 = fmaxf(mx1, __shfl_xor_sync(0xffffffffu, mx1, off));
        }
        float mn0 = fmaxf(m_i[0], mx0), mn1 = fmaxf(m_i[1], mx1);
        float corr0 = __expf(m_i[0] - mn0), corr1 = __expf(m_i[1] - mn1);
        m_i[0] = mn0; m_i[1] = mn1;

        // ---- exp, row sum, write P (tf32) ----
        float rs0 = 0.0f, rs1 = 0.0f;
        #pragma unroll
        for (int nf = 0; nf < 16; nf++) {
            float p0 = __expf(s[nf][0] - mn0);
            float p1 = __expf(s[nf][1] - mn0);
            float p2 = __expf(s[nf][2] - mn1);
            float p3 = __expf(s[nf][3] - mn1);
            rs0 += p0 + p1; rs1 += p2 + p3;
            uint2 u0 = make_uint2(f2tf32(p0), f2tf32(p1));
            uint2 u1 = make_uint2(f2tf32(p2), f2tf32(p3));
            *(uint2*)&Ps[r0 * PLD + nf * 8 + 2 * tg] = u0;
            *(uint2*)&Ps[r1 * PLD + nf * 8 + 2 * tg] = u1;
        }
        #pragma unroll
        for (int off = 1; off <= 2; off <<= 1) {
            rs0 += __shfl_xor_sync(0xffffffffu, rs0, off);
            rs1 += __shfl_xor_sync(0xffffffffu, rs1, off);
        }
        l_i[0] = l_i[0] * corr0 + rs0;
        l_i[1] = l_i[1] * corr1 + rs1;
        #pragma unroll
        for (int nf = 0; nf < 8; nf++) {
            o[nf][0] *= corr0; o[nf][1] *= corr0;
            o[nf][2] *= corr1; o[nf][3] *= corr1;
        }
        __syncwarp();   // P rows are warp-private

        // ---- O += P V ----
        #pragma unroll
        for (int kb = 0; kb < 128; kb += 8) {
            uint32_t a[4];
            a[0] = Ps[r0 * PLD + kb + tg];
            a[1] = Ps[r1 * PLD + kb + tg];
            a[2] = Ps[r0 * PLD + kb + tg + 4];
            a[3] = Ps[r1 * PLD + kb + tg + 4];
            #pragma unroll
            for (int nf = 0; nf < 8; nf++) {
                uint32_t bf[2];
                bf[0] = Vs[(kb + tg) * VLD + nf * 8 + g];
                bf[1] = Vs[(kb + tg + 4) * VLD + nf * 8 + g];
                mma_tf32(o[nf], a, bf);
            }
        }
        __syncwarp();   // done with Ps before next tile overwrites
    }

    float inv0 = 1.0f / l_i[0], inv1 = 1.0f / l_i[1];
    size_t row0 = (size_t)(b * S_ + qt * 128 + r0) * D_ + h * 64;
    size_t row1 = (size_t)(b * S_ + qt * 128 + r1) * D_ + h * 64;
    #pragma unroll
    for (int nf = 0; nf < 8; nf++) {
        int col = nf * 8 + 2 * tg;
        *(float2*)&ctx[row0 + col] = make_float2(o[nf][0] * inv0, o[nf][1] * inv0);
        *(float2*)&ctx[row1 + col] = make_float2(o[nf][2] * inv1, o[nf][3] * inv1);
    }
}

// ---------------- fused residual + LayerNorm ----------------
__global__ __launch_bounds__(256) void ln_kernel(
    const float* __restrict__ a, const float* __restrict__ r,
    const float* __restrict__ g, const float* __restrict__ be,
    float* __restrict__ out) {
    int row = blockIdx.x;
    int t = threadIdx.x;
    float4 x = ((const float4*)a)[(size_t)row * 256 + t];
    if (r) {
        float4 y = ((const float4*)r)[(size_t)row * 256 + t];
        x.x += y.x; x.y += y.y; x.z += y.z; x.w += y.w;
    }
    float s  = x.x + x.y + x.z + x.w;
    float ss = x.x * x.x + x.y * x.y + x.z * x.z + x.w * x.w;
    #pragma unroll
    for (int off = 16; off; off >>= 1) {
        s  += __shfl_xor_sync(0xffffffffu, s,  off);
        ss += __shfl_xor_sync(0xffffffffu, ss, off);
    }
    __shared__ float wsum[8], wsq[8];
    int warp = t >> 5, lane = t & 31;
    if (lane == 0) { wsum[warp] = s; wsq[warp] = ss; }
    __syncthreads();
    s = 0.0f; ss = 0.0f;
    #pragma unroll
    for (int i = 0; i < 8; i++) { s += wsum[i]; ss += wsq[i]; }
    float mean = s * (1.0f / 1024.0f);
    float var  = ss * (1.0f / 1024.0f) - mean * mean;
    float rstd = rsqrtf(var + 1e-5f);
    float4 gg = ((const float4*)g)[t];
    float4 bb = ((const float4*)be)[t];
    float4 o;
    o.x = (x.x - mean) * rstd * gg.x + bb.x;
    o.y = (x.y - mean) * rstd * gg.y + bb.y;
    o.z = (x.z - mean) * rstd * gg.z + bb.z;
    o.w = (x.w - mean) * rstd * gg.w + bb.w;
    ((float4*)out)[(size_t)row * 256 + t] = o;
}

// ---------------- launch ----------------
extern "C" void kernel_launch(void* const* d_in, const int* in_sizes, int n_in,
                              void* d_out, int out_size) {
    (void)in_sizes; (void)n_in; (void)out_size;
    const int*   x    = (const int*)  d_in[0];
    const int*   mask = (const int*)  d_in[1];
    const float* emb  = (const float*)d_in[2];
    const float* wq   = (const float*)d_in[3];
    const float* bq   = (const float*)d_in[4];
    const float* wk   = (const float*)d_in[5];
    const float* bk   = (const float*)d_in[6];
    const float* wv   = (const float*)d_in[7];
    const float* bv   = (const float*)d_in[8];
    const float* wo   = (const float*)d_in[9];
    const float* bo   = (const float*)d_in[10];
    const float* w1   = (const float*)d_in[11];
    const float* b1   = (const float*)d_in[12];
    const float* w2   = (const float*)d_in[13];
    const float* b2   = (const float*)d_in[14];
    const float* g1   = (const float*)d_in[15];
    const float* be1  = (const float*)d_in[16];
    const float* g2   = (const float*)d_in[17];
    const float* be2  = (const float*)d_in[18];
    const float* gf   = (const float*)d_in[19];
    const float* bf   = (const float*)d_in[20];
    float* out = (float*)d_out;

    float *gh, *gq, *gk, *gv, *gctx, *gp, *gff;
    cudaGetSymbolAddress((void**)&gh,   g_h);
    cudaGetSymbolAddress((void**)&gq,   g_q);
    cudaGetSymbolAddress((void**)&gk,   g_k);
    cudaGetSymbolAddress((void**)&gv,   g_v);
    cudaGetSymbolAddress((void**)&gctx, g_ctx);
    cudaGetSymbolAddress((void**)&gp,   g_p);
    cudaGetSymbolAddress((void**)&gff,  g_ff);

    cudaFuncSetAttribute(attn_mma,
                         cudaFuncAttributeMaxDynamicSharedMemorySize,
                         ATTN_SMEM_BYTES);
    cudaFuncSetAttribute(gemm_tf32<0>,
                         cudaFuncAttributeMaxDynamicSharedMemorySize,
                         GEMM_SMEM_BYTES);
    cudaFuncSetAttribute(gemm_tf32<1>,
                         cudaFuncAttributeMaxDynamicSharedMemorySize,
                         GEMM_SMEM_BYTES);
    cudaFuncSetAttribute(gemm_qkv,
                         cudaFuncAttributeMaxDynamicSharedMemorySize,
                         GEMM_SMEM_BYTES);

    embed_kernel<<<(BS_ * D_) / 256, 256>>>(x, emb, gh);

    for (int l = 0; l < L_; l++) {
        const size_t wOff = (size_t)l * D_ * D_;
        gemm_qkv<<<dim3(8, 64, 3), 256, GEMM_SMEM_BYTES>>>(
            gh, wq + wOff, bq + l * D_, wk + wOff, bk + l * D_,
            wv + wOff, bv + l * D_, gq, gk, gv);
        attn_mma<<<dim3(S_ / 128, H_, B_), 256, ATTN_SMEM_BYTES>>>(
            gq, gk, gv, mask, gctx);
        gemm_tf32<0><<<dim3(8, 64), 256, GEMM_SMEM_BYTES>>>(
            gctx, wo + wOff, bo + l * D_, gp, BS_, D_, D_);
        ln_kernel<<<BS_, 256>>>(gh, gp, g1 + l * D_, be1 + l * D_, gh);
        gemm_tf32<1><<<dim3(32, 64), 256, GEMM_SMEM_BYTES>>>(
            gh, w1 + (size_t)l * D_ * DFF_, b1 + l * DFF_, gff, BS_, DFF_, D_);
        gemm_tf32<0><<<dim3(8, 64), 256, GEMM_SMEM_BYTES>>>(
            gff, w2 + (size_t)l * DFF_ * D_, b2 + l * D_, gp, BS_, D_, DFF_);
        ln_kernel<<<BS_, 256>>>(gh, gp, g2 + l * D_, be2 + l * D_, gh);
    }
    ln_kernel<<<BS_, 256>>>(gh, nullptr, gf, bf, out);
}

// round 4
// speedup vs baseline: 2.8940x; 1.1682x over previous
#include <cuda_runtime.h>
#include <math.h>
#include <stdint.h>

// ---------------- problem constants ----------------
constexpr int B_   = 4;
constexpr int S_   = 2048;
constexpr int D_   = 1024;
constexpr int H_   = 16;
constexpr int DFF_ = 4096;
constexpr int L_   = 6;
constexpr int BS_  = B_ * S_;   // 8192 rows

// ---------------- scratch ----------------
__device__ float g_h  [(size_t)BS_ * D_];
__device__ float g_q  [(size_t)BS_ * D_];
__device__ float g_k  [(size_t)BS_ * D_];
__device__ float g_v  [(size_t)BS_ * D_];
__device__ float g_ctx[(size_t)BS_ * D_];
__device__ float g_p  [(size_t)BS_ * D_];
__device__ float g_ff [(size_t)BS_ * DFF_];
// tf32-pre-rounded weights
__device__ float g_cwq[(size_t)L_ * D_ * D_];
__device__ float g_cwk[(size_t)L_ * D_ * D_];
__device__ float g_cwv[(size_t)L_ * D_ * D_];
__device__ float g_cwo[(size_t)L_ * D_ * D_];
__device__ float g_cw1[(size_t)L_ * D_ * DFF_];
__device__ float g_cw2[(size_t)L_ * DFF_ * D_];

// ---------------- tf32 helpers ----------------
__device__ __forceinline__ uint32_t f2tf32(float x) {
    uint32_t r;
    asm("cvt.rna.tf32.f32 %0, %1;" : "=r"(r) : "f"(x));
    return r;
}
__device__ __forceinline__ float rnd32(float x) {
    return __uint_as_float(f2tf32(x));
}
__device__ __forceinline__ void mma_tf32(float* c, const uint32_t* a,
                                         const uint32_t* b) {
    asm volatile(
        "mma.sync.aligned.m16n8k8.row.col.f32.tf32.tf32.f32 "
        "{%0,%1,%2,%3}, {%4,%5,%6,%7}, {%8,%9}, {%0,%1,%2,%3};\n"
        : "+f"(c[0]), "+f"(c[1]), "+f"(c[2]), "+f"(c[3])
        : "r"(a[0]), "r"(a[1]), "r"(a[2]), "r"(a[3]), "r"(b[0]), "r"(b[1]));
}
__device__ __forceinline__ void cp_async16(uint32_t dst, const void* src) {
    asm volatile("cp.async.cg.shared.global [%0], [%1], 16;\n"
                 :: "r"(dst), "l"(src));
}
#define CP_COMMIT() asm volatile("cp.async.commit_group;\n" ::: "memory")
#define CP_WAIT(N)  asm volatile("cp.async.wait_group %0;\n" :: "n"(N) : "memory")

// ---------------- weight pre-round (fp32 -> tf32-exact fp32) --------------
__global__ void tf32_round_kernel(const float* __restrict__ in,
                                  float* __restrict__ out, int n4) {
    int i = blockIdx.x * blockDim.x + threadIdx.x;
    if (i >= n4) return;
    float4 v = ((const float4*)in)[i];
    v.x = rnd32(v.x); v.y = rnd32(v.y); v.z = rnd32(v.z); v.w = rnd32(v.w);
    ((float4*)out)[i] = v;
}

// ---------------- embedding + positional encoding ----------------
__global__ void embed_kernel(const int* __restrict__ x,
                             const float* __restrict__ emb,
                             float* __restrict__ h) {
    int idx = blockIdx.x * blockDim.x + threadIdx.x;
    int row = idx >> 10;
    int d   = idx & (D_ - 1);
    int tok = x[row];
    int s   = row & (S_ - 1);
    float val = emb[(size_t)tok * D_ + d] * 32.0f;
    int i2 = d & ~1;
    float div = expf((float)i2 * (-0.00899447301960227f));
    float ang = (float)s * div;
    float pe = (d & 1) ? cosf(ang) : sinf(ang);
    h[idx] = rnd32(val + pe);   // tf32-exact for downstream GEMMs
}

// ---------------- pipelined tf32 GEMM (cp.async, 4 stages) ---------------
// C = A @ W + bias (opt ReLU). A:(M,K) rm (tf32-exact), W:(K,N) rm (tf32-exact).
// Block 128x128, BK=32, 512 threads = 16 warps (4x4), warp tile 32x32.
constexpr int STAGES  = 4;
constexpr int ALD     = 36;                // A smem row stride (floats)
constexpr int BLD     = 136;               // B smem row stride (floats)
constexpr int A_STAGE = 128 * ALD;         // 4608 floats
constexpr int B_STAGE = 32 * BLD;          // 4352 floats
constexpr int STAGE_F = A_STAGE + B_STAGE; // 8960 floats
constexpr int GEMM_SMEM_BYTES = STAGES * STAGE_F * 4;   // 143360

template<int RELU>
__device__ __forceinline__ void gemm_body(
    const float* __restrict__ A, const float* __restrict__ W,
    const float* __restrict__ bias, float* __restrict__ C,
    int M, int N, int K) {
    extern __shared__ float smf[];
    const uint32_t smem_base = (uint32_t)__cvta_generic_to_shared(smf);

    const int t    = threadIdx.x;
    const int m0   = blockIdx.y * 128;
    const int n0   = blockIdx.x * 128;
    const int warp = t >> 5, lane = t & 31;
    const int wm   = warp >> 2, wn = warp & 3;
    const int g    = lane >> 2, tg = lane & 3;

    // cp.async mappings (each thread copies 2 A-chunks + 2 B-chunks of 16B)
    const int aR  = t >> 3;           // A row (and +64)
    const int aK4 = (t & 7) << 2;     // A col (floats)
    const int bK  = t >> 5;           // B k-row (and +16)
    const int bN4 = (t & 31) << 2;    // B col (floats)

    const float* Ag = A + (size_t)m0 * K;
    const float* Bg = W + n0;

    float acc[2][4][4];
    #pragma unroll
    for (int i = 0; i < 2; i++)
        #pragma unroll
        for (int j = 0; j < 4; j++)
            #pragma unroll
            for (int r = 0; r < 4; r++) acc[i][j][r] = 0.0f;

    auto prefetch = [&](int kt, int stage) {
        const int k0 = kt << 5;
        uint32_t As = smem_base + (stage * STAGE_F) * 4;
        uint32_t Bs = As + A_STAGE * 4;
        cp_async16(As + (aR * ALD + aK4) * 4,
                   Ag + (size_t)aR * K + k0 + aK4);
        cp_async16(As + ((aR + 64) * ALD + aK4) * 4,
                   Ag + (size_t)(aR + 64) * K + k0 + aK4);
        cp_async16(Bs + (bK * BLD + bN4) * 4,
                   Bg + (size_t)(k0 + bK) * N + bN4);
        cp_async16(Bs + ((bK + 16) * BLD + bN4) * 4,
                   Bg + (size_t)(k0 + bK + 16) * N + bN4);
    };

    auto compute = [&](int stage) {
        const uint32_t* As = (const uint32_t*)(smf + stage * STAGE_F);
        const uint32_t* Bs = As + A_STAGE;
        #pragma unroll
        for (int ks = 0; ks < 4; ks++) {
            const int k8 = ks << 3;
            uint32_t a[2][4], b[4][2];
            #pragma unroll
            for (int mf = 0; mf < 2; mf++) {
                const int mb = wm * 32 + mf * 16;
                a[mf][0] = As[(mb + g)     * ALD + k8 + tg];
                a[mf][1] = As[(mb + 8 + g) * ALD + k8 + tg];
                a[mf][2] = As[(mb + g)     * ALD + k8 + tg + 4];
                a[mf][3] = As[(mb + 8 + g) * ALD + k8 + tg + 4];
            }
            #pragma unroll
            for (int nf = 0; nf < 4; nf++) {
                const int nb = wn * 32 + nf * 8 + g;
                b[nf][0] = Bs[(k8 + tg)     * BLD + nb];
                b[nf][1] = Bs[(k8 + tg + 4) * BLD + nb];
            }
            #pragma unroll
            for (int mf = 0; mf < 2; mf++)
                #pragma unroll
                for (int nf = 0; nf < 4; nf++)
                    mma_tf32(acc[mf][nf], a[mf], b[nf]);
        }
    };

    const int nk = K >> 5;
    #pragma unroll
    for (int s = 0; s < STAGES - 1; s++) {
        if (s < nk) prefetch(s, s);
        CP_COMMIT();
    }

    for (int kt = 0; kt < nk; kt++) {
        CP_WAIT(STAGES - 2);
        __syncthreads();
        const int nt = kt + STAGES - 1;
        if (nt < nk) prefetch(nt, nt & (STAGES - 1));
        CP_COMMIT();
        compute(kt & (STAGES - 1));
    }

    // epilogue (bias + opt ReLU + tf32 rounding)
    #pragma unroll
    for (int mf = 0; mf < 2; mf++) {
        int r0 = m0 + wm * 32 + mf * 16 + g;
        int r1 = r0 + 8;
        #pragma unroll
        for (int nf = 0; nf < 4; nf++) {
            int col = n0 + wn * 32 + nf * 8 + tg * 2;
            float2 bb = *(const float2*)&bias[col];
            float2 o0, o1;
            o0.x = acc[mf][nf][0] + bb.x;
            o0.y = acc[mf][nf][1] + bb.y;
            o1.x = acc[mf][nf][2] + bb.x;
            o1.y = acc[mf][nf][3] + bb.y;
            if (RELU) {
                o0.x = fmaxf(o0.x, 0.0f); o0.y = fmaxf(o0.y, 0.0f);
                o1.x = fmaxf(o1.x, 0.0f); o1.y = fmaxf(o1.y, 0.0f);
            }
            o0.x = rnd32(o0.x); o0.y = rnd32(o0.y);
            o1.x = rnd32(o1.x); o1.y = rnd32(o1.y);
            *(float2*)&C[(size_t)r0 * N + col] = o0;
            *(float2*)&C[(size_t)r1 * N + col] = o1;
        }
    }
}

template<int RELU>
__global__ __launch_bounds__(512) void gemm_tf32(
    const float* __restrict__ A, const float* __restrict__ W,
    const float* __restrict__ bias, float* __restrict__ C,
    int M, int N, int K) {
    gemm_body<RELU>(A, W, bias, C, M, N, K);
}

__global__ __launch_bounds__(512) void gemm_qkv(
    const float* __restrict__ A,
    const float* __restrict__ wq, const float* __restrict__ bq,
    const float* __restrict__ wk, const float* __restrict__ bk,
    const float* __restrict__ wv, const float* __restrict__ bv,
    float* __restrict__ oq, float* __restrict__ ok, float* __restrict__ ov) {
    const float* W; const float* bias; float* C;
    if (blockIdx.z == 0)      { W = wq; bias = bq; C = oq; }
    else if (blockIdx.z == 1) { W = wk; bias = bk; C = ok; }
    else                      { W = wv; bias = bv; C = ov; }
    gemm_body<0>(A, W, bias, C, BS_, D_, D_);
}

// ---------------- tensor-core flash attention (as R3, + tf32 out) --------
constexpr int QLD = 68;
constexpr int VLD = 72;
constexpr int PLD = 132;
constexpr int ATTN_SMEM_BYTES =
    (128 * QLD * 2 + 128 * VLD + 128 * PLD) * 4 + S_ * 4;

__global__ __launch_bounds__(256) void attn_mma(
    const float* __restrict__ Q, const float* __restrict__ K,
    const float* __restrict__ V, const int* __restrict__ mask,
    float* __restrict__ ctx) {
    extern __shared__ uint32_t sm[];
    uint32_t* Qs = sm;
    uint32_t* Ks = Qs + 128 * QLD;
    uint32_t* Vs = Ks + 128 * QLD;
    uint32_t* Ps = Vs + 128 * VLD;
    int*     msk = (int*)(Ps + 128 * PLD);

    const int qt = blockIdx.x, h = blockIdx.y, b = blockIdx.z;
    const int t = threadIdx.x, w = t >> 5, lane = t & 31;
    const int g = lane >> 2, tg = lane & 3;
    const int r0 = w * 16 + g, r1 = r0 + 8;

    for (int i = t; i < S_; i += 256) msk[i] = mask[b * S_ + i];
    for (int i = t; i < 128 * 16; i += 256) {
        int r = i >> 4, c4 = (i & 15) << 2;
        float4 qv = *(const float4*)&Q[(size_t)(b * S_ + qt * 128 + r) * D_ +
                                       h * 64 + c4];
        uint32_t* dst = &Qs[r * QLD + c4];
        dst[0] = f2tf32(qv.x * 0.125f);
        dst[1] = f2tf32(qv.y * 0.125f);
        dst[2] = f2tf32(qv.z * 0.125f);
        dst[3] = f2tf32(qv.w * 0.125f);
    }

    float m_i[2] = {-INFINITY, -INFINITY};
    float l_i[2] = {0.0f, 0.0f};
    float o[8][4];
    #pragma unroll
    for (int nf = 0; nf < 8; nf++)
        #pragma unroll
        for (int r = 0; r < 4; r++) o[nf][r] = 0.0f;

    for (int kt = 0; kt < S_ / 128; kt++) {
        __syncthreads();
        for (int i = t; i < 128 * 16; i += 256) {
            int r = i >> 4, c4 = (i & 15) << 2;
            size_t gofs = (size_t)(b * S_ + kt * 128 + r) * D_ + h * 64 + c4;
            float4 kv = *(const float4*)&K[gofs];
            float4 vv = *(const float4*)&V[gofs];
            uint32_t* kd = &Ks[r * QLD + c4];
            kd[0] = f2tf32(kv.x); kd[1] = f2tf32(kv.y);
            kd[2] = f2tf32(kv.z); kd[3] = f2tf32(kv.w);
            uint32_t* vd = &Vs[r * VLD + c4];
            vd[0] = f2tf32(vv.x); vd[1] = f2tf32(vv.y);
            vd[2] = f2tf32(vv.z); vd[3] = f2tf32(vv.w);
        }
        __syncthreads();

        float s[16][4];
        #pragma unroll
        for (int nf = 0; nf < 16; nf++)
            #pragma unroll
            for (int r = 0; r < 4; r++) s[nf][r] = 0.0f;

        #pragma unroll
        for (int kb = 0; kb < 64; kb += 8) {
            uint32_t a[4];
            a[0] = Qs[r0 * QLD + kb + tg];
            a[1] = Qs[r1 * QLD + kb + tg];
            a[2] = Qs[r0 * QLD + kb + tg + 4];
            a[3] = Qs[r1 * QLD + kb + tg + 4];
            #pragma unroll
            for (int nf = 0; nf < 16; nf++) {
                uint32_t bf[2];
                bf[0] = Ks[(nf * 8 + g) * QLD + kb + tg];
                bf[1] = Ks[(nf * 8 + g) * QLD + kb + tg + 4];
                mma_tf32(s[nf], a, bf);
            }
        }

        float mx0 = -INFINITY, mx1 = -INFINITY;
        #pragma unroll
        for (int nf = 0; nf < 16; nf++) {
            int c = kt * 128 + nf * 8 + 2 * tg;
            if (msk[c] == 0)     { s[nf][0] = -1e9f; s[nf][2] = -1e9f; }
            if (msk[c + 1] == 0) { s[nf][1] = -1e9f; s[nf][3] = -1e9f; }
            mx0 = fmaxf(mx0, fmaxf(s[nf][0], s[nf][1]));
            mx1 = fmaxf(mx1, fmaxf(s[nf][2], s[nf][3]));
        }
        #pragma unroll
        for (int off = 1; off <= 2; off <<= 1) {
            mx0 = fmaxf(mx0, __shfl_xor_sync(0xffffffffu, mx0, off));
            mx1 = fmaxf(mx1, __shfl_xor_sync(0xffffffffu, mx1, off));
        }
        float mn0 = fmaxf(m_i[0], mx0), mn1 = fmaxf(m_i[1], mx1);
        float corr0 = __expf(m_i[0] - mn0), corr1 = __expf(m_i[1] - mn1);
        m_i[0] = mn0; m_i[1] = mn1;

        float rs0 = 0.0f, rs1 = 0.0f;
        #pragma unroll
        for (int nf = 0; nf < 16; nf++) {
            float p0 = __expf(s[nf][0] - mn0);
            float p1 = __expf(s[nf][1] - mn0);
            float p2 = __expf(s[nf][2] - mn1);
            float p3 = __expf(s[nf][3] - mn1);
            rs0 += p0 + p1; rs1 += p2 + p3;
            uint2 u0 = make_uint2(f2tf32(p0), f2tf32(p1));
            uint2 u1 = make_uint2(f2tf32(p2), f2tf32(p3));
            *(uint2*)&Ps[r0 * PLD + nf * 8 + 2 * tg] = u0;
            *(uint2*)&Ps[r1 * PLD + nf * 8 + 2 * tg] = u1;
        }
        #pragma unroll
        for (int off = 1; off <= 2; off <<= 1) {
            rs0 += __shfl_xor_sync(0xffffffffu, rs0, off);
            rs1 += __shfl_xor_sync(0xffffffffu, rs1, off);
        }
        l_i[0] = l_i[0] * corr0 + rs0;
        l_i[1] = l_i[1] * corr1 + rs1;
        #pragma unroll
        for (int nf = 0; nf < 8; nf++) {
            o[nf][0] *= corr0; o[nf][1] *= corr0;
            o[nf][2] *= corr1; o[nf][3] *= corr1;
        }
        __syncwarp();

        #pragma unroll
        for (int kb = 0; kb < 128; kb += 8) {
            uint32_t a[4];
            a[0] = Ps[r0 * PLD + kb + tg];
            a[1] = Ps[r1 * PLD + kb + tg];
            a[2] = Ps[r0 * PLD + kb + tg + 4];
            a[3] = Ps[r1 * PLD + kb + tg + 4];
            #pragma unroll
            for (int nf = 0; nf < 8; nf++) {
                uint32_t bf[2];
                bf[0] = Vs[(kb + tg) * VLD + nf * 8 + g];
                bf[1] = Vs[(kb + tg + 4) * VLD + nf * 8 + g];
                mma_tf32(o[nf], a, bf);
            }
        }
        __syncwarp();
    }

    float inv0 = 1.0f / l_i[0], inv1 = 1.0f / l_i[1];
    size_t row0 = (size_t)(b * S_ + qt * 128 + r0) * D_ + h * 64;
    size_t row1 = (size_t)(b * S_ + qt * 128 + r1) * D_ + h * 64;
    #pragma unroll
    for (int nf = 0; nf < 8; nf++) {
        int col = nf * 8 + 2 * tg;
        *(float2*)&ctx[row0 + col] =
            make_float2(rnd32(o[nf][0] * inv0), rnd32(o[nf][1] * inv0));
        *(float2*)&ctx[row1 + col] =
            make_float2(rnd32(o[nf][2] * inv1), rnd32(o[nf][3] * inv1));
    }
}

// ---------------- fused residual + LayerNorm ----------------
template<int ROUND>
__global__ __launch_bounds__(256) void ln_kernel(
    const float* __restrict__ a, const float* __restrict__ r,
    const float* __restrict__ g, const float* __restrict__ be,
    float* __restrict__ out) {
    int row = blockIdx.x;
    int t = threadIdx.x;
    float4 x = ((const float4*)a)[(size_t)row * 256 + t];
    if (r) {
        float4 y = ((const float4*)r)[(size_t)row * 256 + t];
        x.x += y.x; x.y += y.y; x.z += y.z; x.w += y.w;
    }
    float s  = x.x + x.y + x.z + x.w;
    float ss = x.x * x.x + x.y * x.y + x.z * x.z + x.w * x.w;
    #pragma unroll
    for (int off = 16; off; off >>= 1) {
        s  += __shfl_xor_sync(0xffffffffu, s,  off);
        ss += __shfl_xor_sync(0xffffffffu, ss, off);
    }
    __shared__ float wsum[8], wsq[8];
    int warp = t >> 5, lane = t & 31;
    if (lane == 0) { wsum[warp] = s; wsq[warp] = ss; }
    __syncthreads();
    s = 0.0f; ss = 0.0f;
    #pragma unroll
    for (int i = 0; i < 8; i++) { s += wsum[i]; ss += wsq[i]; }
    float mean = s * (1.0f / 1024.0f);
    float var  = ss * (1.0f / 1024.0f) - mean * mean;
    float rstd = rsqrtf(var + 1e-5f);
    float4 gg = ((const float4*)g)[t];
    float4 bb = ((const float4*)be)[t];
    float4 o;
    o.x = (x.x - mean) * rstd * gg.x + bb.x;
    o.y = (x.y - mean) * rstd * gg.y + bb.y;
    o.z = (x.z - mean) * rstd * gg.z + bb.z;
    o.w = (x.w - mean) * rstd * gg.w + bb.w;
    if (ROUND) {
        o.x = rnd32(o.x); o.y = rnd32(o.y);
        o.z = rnd32(o.z); o.w = rnd32(o.w);
    }
    ((float4*)out)[(size_t)row * 256 + t] = o;
}

// ---------------- launch ----------------
extern "C" void kernel_launch(void* const* d_in, const int* in_sizes, int n_in,
                              void* d_out, int out_size) {
    (void)in_sizes; (void)n_in; (void)out_size;
    const int*   x    = (const int*)  d_in[0];
    const int*   mask = (const int*)  d_in[1];
    const float* emb  = (const float*)d_in[2];
    const float* wq   = (const float*)d_in[3];
    const float* bq   = (const float*)d_in[4];
    const float* wk   = (const float*)d_in[5];
    const float* bk   = (const float*)d_in[6];
    const float* wv   = (const float*)d_in[7];
    const float* bv   = (const float*)d_in[8];
    const float* wo   = (const float*)d_in[9];
    const float* bo   = (const float*)d_in[10];
    const float* w1   = (const float*)d_in[11];
    const float* b1   = (const float*)d_in[12];
    const float* w2   = (const float*)d_in[13];
    const float* b2   = (const float*)d_in[14];
    const float* g1   = (const float*)d_in[15];
    const float* be1  = (const float*)d_in[16];
    const float* g2   = (const float*)d_in[17];
    const float* be2  = (const float*)d_in[18];
    const float* gf   = (const float*)d_in[19];
    const float* bf   = (const float*)d_in[20];
    float* out = (float*)d_out;

    float *gh, *gq, *gk, *gv, *gctx, *gp, *gff;
    float *cwq, *cwk, *cwv, *cwo, *cw1, *cw2;
    cudaGetSymbolAddress((void**)&gh,   g_h);
    cudaGetSymbolAddress((void**)&gq,   g_q);
    cudaGetSymbolAddress((void**)&gk,   g_k);
    cudaGetSymbolAddress((void**)&gv,   g_v);
    cudaGetSymbolAddress((void**)&gctx, g_ctx);
    cudaGetSymbolAddress((void**)&gp,   g_p);
    cudaGetSymbolAddress((void**)&gff,  g_ff);
    cudaGetSymbolAddress((void**)&cwq,  g_cwq);
    cudaGetSymbolAddress((void**)&cwk,  g_cwk);
    cudaGetSymbolAddress((void**)&cwv,  g_cwv);
    cudaGetSymbolAddress((void**)&cwo,  g_cwo);
    cudaGetSymbolAddress((void**)&cw1,  g_cw1);
    cudaGetSymbolAddress((void**)&cw2,  g_cw2);

    cudaFuncSetAttribute(attn_mma,
                         cudaFuncAttributeMaxDynamicSharedMemorySize,
                         ATTN_SMEM_BYTES);
    cudaFuncSetAttribute(gemm_tf32<0>,
                         cudaFuncAttributeMaxDynamicSharedMemorySize,
                         GEMM_SMEM_BYTES);
    cudaFuncSetAttribute(gemm_tf32<1>,
                         cudaFuncAttributeMaxDynamicSharedMemorySize,
                         GEMM_SMEM_BYTES);
    cudaFuncSetAttribute(gemm_qkv,
                         cudaFuncAttributeMaxDynamicSharedMemorySize,
                         GEMM_SMEM_BYTES);

    // weight pre-round to tf32-exact
    const int nDD = L_ * D_ * D_ / 4, nDF = L_ * D_ * DFF_ / 4;
    tf32_round_kernel<<<(nDD + 255) / 256, 256>>>(wq, cwq, nDD);
    tf32_round_kernel<<<(nDD + 255) / 256, 256>>>(wk, cwk, nDD);
    tf32_round_kernel<<<(nDD + 255) / 256, 256>>>(wv, cwv, nDD);
    tf32_round_kernel<<<(nDD + 255) / 256, 256>>>(wo, cwo, nDD);
    tf32_round_kernel<<<(nDF + 255) / 256, 256>>>(w1, cw1, nDF);
    tf32_round_kernel<<<(nDF + 255) / 256, 256>>>(w2, cw2, nDF);

    embed_kernel<<<(BS_ * D_) / 256, 256>>>(x, emb, gh);

    for (int l = 0; l < L_; l++) {
        const size_t wOff = (size_t)l * D_ * D_;
        const size_t fOff = (size_t)l * D_ * DFF_;
        gemm_qkv<<<dim3(8, 64, 3), 512, GEMM_SMEM_BYTES>>>(
            gh, cwq + wOff, bq + l * D_, cwk + wOff, bk + l * D_,
            cwv + wOff, bv + l * D_, gq, gk, gv);
        attn_mma<<<dim3(S_ / 128, H_, B_), 256, ATTN_SMEM_BYTES>>>(
            gq, gk, gv, mask, gctx);
        gemm_tf32<0><<<dim3(8, 64), 512, GEMM_SMEM_BYTES>>>(
            gctx, cwo + wOff, bo + l * D_, gp, BS_, D_, D_);
        ln_kernel<1><<<BS_, 256>>>(gh, gp, g1 + l * D_, be1 + l * D_, gh);
        gemm_tf32<1><<<dim3(32, 64), 512, GEMM_SMEM_BYTES>>>(
            gh, cw1 + fOff, b1 + l * DFF_, gff, BS_, DFF_, D_);
        gemm_tf32<0><<<dim3(8, 64), 512, GEMM_SMEM_BYTES>>>(
            gff, cw2 + fOff, b2 + l * D_, gp, BS_, D_, DFF_);
        ln_kernel<1><<<BS_, 256>>>(gh, gp, g2 + l * D_, be2 + l * D_, gh);
    }
    ln_kernel<0><<<BS_, 256>>>(gh, nullptr, gf, bf, out);
}